// round 2
// baseline (speedup 1.0000x reference)
#include <cuda_runtime.h>
#include <math.h>

#define N_NODES 8192
#define N_EDGE  512
#define DIM     1024
#define HID     1024

// output float offsets: (edges, H, dots)
#define E_OFF 0
#define H_OFF (N_EDGE * DIM)                 // 524288
#define DOTS_OFF (H_OFF + N_NODES * N_EDGE)  // 4718592

// ---------------- scratch (static device memory; no allocations) ----------------
__device__ float g_x  [N_NODES * DIM];
__device__ float g_k  [N_NODES * DIM];
__device__ float g_v  [N_NODES * DIM];
__device__ float g_q2 [N_NODES * DIM];
__device__ float g_e0 [N_EDGE * DIM];
__device__ float g_q  [N_EDGE * DIM];
__device__ float g_cat[N_EDGE * 2 * DIM];
__device__ float g_h1 [N_EDGE * HID];
__device__ float g_k2 [N_EDGE * DIM];
__device__ float g_dv [N_NODES * N_EDGE];

// ---------------- reduction helpers ----------------
__device__ __forceinline__ float blockReduceSum(float val, float* shm) {
    int lane = threadIdx.x & 31, wid = threadIdx.x >> 5;
    #pragma unroll
    for (int o = 16; o > 0; o >>= 1) val += __shfl_down_sync(0xffffffffu, val, o);
    if (lane == 0) shm[wid] = val;
    __syncthreads();
    int nw = (blockDim.x + 31) >> 5;
    val = (threadIdx.x < nw) ? shm[threadIdx.x] : 0.f;
    if (wid == 0) {
        #pragma unroll
        for (int o = 16; o > 0; o >>= 1) val += __shfl_down_sync(0xffffffffu, val, o);
        if (lane == 0) shm[0] = val;
    }
    __syncthreads();
    float r = shm[0];
    __syncthreads();
    return r;
}

__device__ __forceinline__ float blockReduceMax(float val, float* shm) {
    int lane = threadIdx.x & 31, wid = threadIdx.x >> 5;
    #pragma unroll
    for (int o = 16; o > 0; o >>= 1) val = fmaxf(val, __shfl_down_sync(0xffffffffu, val, o));
    if (lane == 0) shm[wid] = val;
    __syncthreads();
    int nw = (blockDim.x + 31) >> 5;
    val = (threadIdx.x < nw) ? shm[threadIdx.x] : -INFINITY;
    if (wid == 0) {
        #pragma unroll
        for (int o = 16; o > 0; o >>= 1) val = fmaxf(val, __shfl_down_sync(0xffffffffu, val, o));
        if (lane == 0) shm[0] = val;
    }
    __syncthreads();
    float r = shm[0];
    __syncthreads();
    return r;
}

__device__ __forceinline__ unsigned blockReduceSumU(unsigned val, unsigned* shm) {
    int lane = threadIdx.x & 31, wid = threadIdx.x >> 5;
    #pragma unroll
    for (int o = 16; o > 0; o >>= 1) val += __shfl_down_sync(0xffffffffu, val, o);
    if (lane == 0) shm[wid] = val;
    __syncthreads();
    int nw = (blockDim.x + 31) >> 5;
    val = (threadIdx.x < nw) ? shm[threadIdx.x] : 0u;
    if (wid == 0) {
        #pragma unroll
        for (int o = 16; o > 0; o >>= 1) val += __shfl_down_sync(0xffffffffu, val, o);
        if (lane == 0) shm[0] = val;
    }
    __syncthreads();
    unsigned r = shm[0];
    __syncthreads();
    return r;
}

// order-preserving float -> uint key
__device__ __forceinline__ unsigned fkey(float f) {
    unsigned u = __float_as_uint(f);
    return u ^ (((int)u >> 31) | 0x80000000u);
}

// ---------------- layernorm: out = (x-mean)/sqrt(var+1e-5)*g + b ----------------
__global__ __launch_bounds__(256) void ln_kernel(
    const float* __restrict__ in, const float* __restrict__ g, const float* __restrict__ b,
    float* __restrict__ out, int ncols)
{
    __shared__ float shm[32];
    int row = blockIdx.x;
    const float* x = in + (size_t)row * ncols;
    float* y = out + (size_t)row * ncols;
    float s = 0.f, s2 = 0.f;
    for (int i = threadIdx.x; i < ncols; i += blockDim.x) { float v = x[i]; s += v; s2 += v * v; }
    float S  = blockReduceSum(s,  shm);
    float S2 = blockReduceSum(s2, shm);
    float mean = S / ncols;
    float var  = S2 / ncols - mean * mean;
    float inv  = rsqrtf(var + 1e-5f);
    for (int i = threadIdx.x; i < ncols; i += blockDim.x)
        y[i] = (x[i] - mean) * inv * g[i] + b[i];
}

// ---------------- edge sample + layernorm ----------------
__global__ __launch_bounds__(256) void edge_ln_kernel(
    const float* __restrict__ noise, const float* __restrict__ mu, const float* __restrict__ ls,
    const float* __restrict__ g, const float* __restrict__ b, float* __restrict__ out)
{
    __shared__ float shm[32];
    int row = blockIdx.x;
    const float* nz = noise + (size_t)row * DIM;
    float* y = out + (size_t)row * DIM;
    float s = 0.f, s2 = 0.f;
    for (int i = threadIdx.x; i < DIM; i += blockDim.x) {
        float v = mu[i] + expf(ls[i]) * nz[i];
        s += v; s2 += v * v;
    }
    float S  = blockReduceSum(s,  shm);
    float S2 = blockReduceSum(s2, shm);
    float mean = S / DIM;
    float var  = S2 / DIM - mean * mean;
    float inv  = rsqrtf(var + 1e-5f);
    for (int i = threadIdx.x; i < DIM; i += blockDim.x) {
        float v = mu[i] + expf(ls[i]) * nz[i];
        y[i] = (v - mean) * inv * g[i] + b[i];
    }
}

// ---------------- SGEMM NN: C[M,Nc] = act(A[M,K] @ B[K,Nc] + bias) ----------------
// BM=BN=64, BK=16, 256 threads, 4x4 microtile with stride-16 mapping (conflict free)
template <int RELU>
__global__ __launch_bounds__(256) void gemm_nn(
    const float* __restrict__ A, const float* __restrict__ B, const float* __restrict__ bias,
    float* __restrict__ C, int M, int Nc, int K)
{
    __shared__ float As[16][65];
    __shared__ float Bs[16][65];
    int bm = blockIdx.y * 64, bn = blockIdx.x * 64;
    int tid = threadIdx.x;
    int tx = tid & 15, ty = tid >> 4;
    float acc[4][4] = {};
    for (int k0 = 0; k0 < K; k0 += 16) {
        #pragma unroll
        for (int i = 0; i < 4; i++) {
            int e = tid + i * 256; int r = e >> 4, kk = e & 15;
            As[kk][r] = A[(size_t)(bm + r) * K + k0 + kk];
        }
        #pragma unroll
        for (int i = 0; i < 4; i++) {
            int e = tid + i * 256; int kk = e >> 6, c = e & 63;
            Bs[kk][c] = B[(size_t)(k0 + kk) * Nc + bn + c];
        }
        __syncthreads();
        #pragma unroll
        for (int kk = 0; kk < 16; kk++) {
            float a0[4], b0[4];
            #pragma unroll
            for (int i = 0; i < 4; i++) a0[i] = As[kk][ty + i * 16];
            #pragma unroll
            for (int j = 0; j < 4; j++) b0[j] = Bs[kk][tx + j * 16];
            #pragma unroll
            for (int i = 0; i < 4; i++)
                #pragma unroll
                for (int j = 0; j < 4; j++)
                    acc[i][j] = fmaf(a0[i], b0[j], acc[i][j]);
        }
        __syncthreads();
    }
    #pragma unroll
    for (int i = 0; i < 4; i++) {
        int r = bm + ty + i * 16;
        #pragma unroll
        for (int j = 0; j < 4; j++) {
            int c = bn + tx + j * 16;
            float v = acc[i][j] + bias[c];
            if (RELU) v = fmaxf(v, 0.f);
            C[(size_t)r * Nc + c] = v;
        }
    }
}

// ---------------- SGEMM NT: C[M,Nn] = alpha * A[M,K] @ B[Nn,K]^T ----------------
__global__ __launch_bounds__(256) void gemm_nt(
    const float* __restrict__ A, const float* __restrict__ B,
    float* __restrict__ C, int M, int Nn, int K, float alpha)
{
    __shared__ float As[16][65];
    __shared__ float Bs[16][65];
    int bm = blockIdx.y * 64, bn = blockIdx.x * 64;
    int tid = threadIdx.x;
    int tx = tid & 15, ty = tid >> 4;
    float acc[4][4] = {};
    for (int k0 = 0; k0 < K; k0 += 16) {
        #pragma unroll
        for (int i = 0; i < 4; i++) {
            int e = tid + i * 256; int r = e >> 4, kk = e & 15;
            As[kk][r] = A[(size_t)(bm + r) * K + k0 + kk];
        }
        #pragma unroll
        for (int i = 0; i < 4; i++) {
            int e = tid + i * 256; int r = e >> 4, kk = e & 15;
            Bs[kk][r] = B[(size_t)(bn + r) * K + k0 + kk];
        }
        __syncthreads();
        #pragma unroll
        for (int kk = 0; kk < 16; kk++) {
            float a0[4], b0[4];
            #pragma unroll
            for (int i = 0; i < 4; i++) a0[i] = As[kk][ty + i * 16];
            #pragma unroll
            for (int j = 0; j < 4; j++) b0[j] = Bs[kk][tx + j * 16];
            #pragma unroll
            for (int i = 0; i < 4; i++)
                #pragma unroll
                for (int j = 0; j < 4; j++)
                    acc[i][j] = fmaf(a0[i], b0[j], acc[i][j]);
        }
        __syncthreads();
    }
    #pragma unroll
    for (int i = 0; i < 4; i++) {
        int r = bm + ty + i * 16;
        #pragma unroll
        for (int j = 0; j < 4; j++) {
            int c = bn + tx + j * 16;
            C[(size_t)r * Nn + c] = alpha * acc[i][j];
        }
    }
}

// ---------------- copy e0 into first half of cat buffer ----------------
__global__ __launch_bounds__(256) void cat_copy_kernel(const float* __restrict__ e0, float* __restrict__ cat)
{
    int row = blockIdx.x;
    for (int c = threadIdx.x; c < DIM; c += blockDim.x)
        cat[(size_t)row * (2 * DIM) + c] = e0[(size_t)row * DIM + c];
}

// ---------------- per-row: softmax(dots) + eps, renorm, top-k mask, updates = attn @ v ----
// one block per edge row (512 rows), row length 8192
__global__ __launch_bounds__(256) void attn_update_kernel(
    const float* __restrict__ dots, const float* __restrict__ v,
    const int* __restrict__ kn_ptr, float* __restrict__ cat_out)
{
    __shared__ float sval[N_NODES];       // 32 KB
    __shared__ float shmf[32];
    __shared__ unsigned shmu[32];
    __shared__ int   sel_idx[128];
    __shared__ float sel_w[128];
    __shared__ unsigned scount, stie;

    int row = blockIdx.x;
    int k = kn_ptr[0];
    if (k > 128) k = 128;
    const float* dr = dots + (size_t)row * N_NODES;

    for (int i = threadIdx.x; i < N_NODES; i += blockDim.x) sval[i] = dr[i];
    __syncthreads();

    // softmax stats
    float m = -INFINITY;
    for (int i = threadIdx.x; i < N_NODES; i += blockDim.x) m = fmaxf(m, sval[i]);
    float rowmax = blockReduceMax(m, shmf);
    float s = 0.f;
    for (int i = threadIdx.x; i < N_NODES; i += blockDim.x) s += expf(sval[i] - rowmax);
    float sumexp = blockReduceSum(s, shmf);
    float invsum = 1.f / sumexp;

    // exact k-th largest via bitwise bisection on monotone keys
    unsigned lo = 0u, hi = 0xFFFFFFFFu;
    while (lo < hi) {
        unsigned mid = lo + ((hi - lo) >> 1) + ((hi - lo) & 1u);   // ceil midpoint
        unsigned c = 0;
        for (int i = threadIdx.x; i < N_NODES; i += blockDim.x)
            if (fkey(sval[i]) >= mid) c++;
        c = blockReduceSumU(c, shmu);
        if (c >= (unsigned)k) lo = mid; else hi = mid - 1u;
    }
    unsigned Tth = lo;

    if (threadIdx.x == 0) { scount = 0u; }
    __syncthreads();
    for (int i = threadIdx.x; i < N_NODES; i += blockDim.x) {
        if (fkey(sval[i]) > Tth) {
            unsigned p = atomicAdd(&scount, 1u);
            if (p < (unsigned)k) sel_idx[p] = i;
        }
    }
    __syncthreads();
    if (threadIdx.x == 0) stie = scount;
    __syncthreads();
    for (int i = threadIdx.x; i < N_NODES; i += blockDim.x) {
        if (fkey(sval[i]) == Tth) {
            unsigned p = atomicAdd(&stie, 1u);
            if (p < (unsigned)k) sel_idx[p] = i;
        }
    }
    __syncthreads();

    // weights: a = (softmax + eps) / (1 + N*eps)
    float renorm = 1.f / (1.f + (float)N_NODES * 1e-8f);
    for (int sI = threadIdx.x; sI < k; sI += blockDim.x) {
        int idx = sel_idx[sI];
        sel_w[sI] = (expf(sval[idx] - rowmax) * invsum + 1e-8f) * renorm;
    }
    __syncthreads();

    // updates row = sum_sel w * v[idx,:]  -> second half of cat buffer
    float acc[4] = {0.f, 0.f, 0.f, 0.f};
    for (int sI = 0; sI < k; sI++) {
        int idx = sel_idx[sI];
        float w = sel_w[sI];
        const float* vr = v + (size_t)idx * DIM;
        #pragma unroll
        for (int j = 0; j < 4; j++)
            acc[j] = fmaf(w, __ldg(vr + threadIdx.x + j * 256), acc[j]);
    }
    #pragma unroll
    for (int j = 0; j < 4; j++)
        cat_out[(size_t)row * (2 * DIM) + DIM + threadIdx.x + j * 256] = acc[j];
}

// ---------------- per-row: H = mask_topk(softmax(dots_v), k_e), row length 512 ----------------
__global__ __launch_bounds__(128) void h_kernel(
    const float* __restrict__ dv, const int* __restrict__ ke_ptr, float* __restrict__ Hout)
{
    __shared__ float sval[N_EDGE];
    __shared__ float shmf[32];
    __shared__ unsigned shmu[32];
    __shared__ unsigned scount, stie;

    int row = blockIdx.x;
    int k = ke_ptr[0];
    if (k > 128) k = 128;
    const float* dr = dv + (size_t)row * N_EDGE;
    for (int i = threadIdx.x; i < N_EDGE; i += blockDim.x) sval[i] = dr[i];
    __syncthreads();

    float m = -INFINITY;
    for (int i = threadIdx.x; i < N_EDGE; i += blockDim.x) m = fmaxf(m, sval[i]);
    float rowmax = blockReduceMax(m, shmf);
    float s = 0.f;
    for (int i = threadIdx.x; i < N_EDGE; i += blockDim.x) s += expf(sval[i] - rowmax);
    float sumexp = blockReduceSum(s, shmf);
    float invsum = 1.f / sumexp;

    unsigned lo = 0u, hi = 0xFFFFFFFFu;
    while (lo < hi) {
        unsigned mid = lo + ((hi - lo) >> 1) + ((hi - lo) & 1u);
        unsigned c = 0;
        for (int i = threadIdx.x; i < N_EDGE; i += blockDim.x)
            if (fkey(sval[i]) >= mid) c++;
        c = blockReduceSumU(c, shmu);
        if (c >= (unsigned)k) lo = mid; else hi = mid - 1u;
    }
    unsigned Tth = lo;

    // count strictly-greater, allocate tie slots
    unsigned cg = 0;
    for (int i = threadIdx.x; i < N_EDGE; i += blockDim.x)
        if (fkey(sval[i]) > Tth) cg++;
    unsigned cnt_gt = blockReduceSumU(cg, shmu);
    unsigned needed = (unsigned)k - cnt_gt;
    if (threadIdx.x == 0) { scount = 0u; stie = 0u; }
    __syncthreads();

    float* hr = Hout + (size_t)row * N_EDGE;
    for (int i = threadIdx.x; i < N_EDGE; i += blockDim.x) {
        unsigned ky = fkey(sval[i]);
        bool sel = false;
        if (ky > Tth) sel = true;
        else if (ky == Tth) {
            unsigned p = atomicAdd(&stie, 1u);
            sel = (p < needed);
        }
        hr[i] = sel ? expf(sval[i] - rowmax) * invsum : 0.f;
    }
}

// ---------------- launch ----------------
extern "C" void kernel_launch(void* const* d_in, const int* in_sizes, int n_in,
                              void* d_out, int out_size)
{
    const float* inputs  = (const float*)d_in[0];
    const float* noise   = (const float*)d_in[1];
    const float* emu     = (const float*)d_in[2];
    const float* elogsig = (const float*)d_in[3];
    const float* Wq = (const float*)d_in[4];  const float* bq = (const float*)d_in[5];
    const float* Wk = (const float*)d_in[6];  const float* bk = (const float*)d_in[7];
    const float* Wv = (const float*)d_in[8];  const float* bv = (const float*)d_in[9];
    const float* W1 = (const float*)d_in[10]; const float* b1 = (const float*)d_in[11];
    const float* W2 = (const float*)d_in[12]; const float* b2 = (const float*)d_in[13];
    const float* g_in = (const float*)d_in[14]; const float* b_in = (const float*)d_in[15];
    const float* g_e  = (const float*)d_in[16]; const float* b_e  = (const float*)d_in[17];
    const int* kn = (const int*)d_in[18];
    const int* ke = (const int*)d_in[19];

    float* out = (float*)d_out;
    float* out_edges = out + E_OFF;
    float* out_H     = out + H_OFF;
    float* out_dots  = out + DOTS_OFF;

    float* px  = nullptr; cudaGetSymbolAddress((void**)&px,  g_x);
    float* pk  = nullptr; cudaGetSymbolAddress((void**)&pk,  g_k);
    float* pv  = nullptr; cudaGetSymbolAddress((void**)&pv,  g_v);
    float* pq2 = nullptr; cudaGetSymbolAddress((void**)&pq2, g_q2);
    float* pe0 = nullptr; cudaGetSymbolAddress((void**)&pe0, g_e0);
    float* pq  = nullptr; cudaGetSymbolAddress((void**)&pq,  g_q);
    float* pcat= nullptr; cudaGetSymbolAddress((void**)&pcat,g_cat);
    float* ph1 = nullptr; cudaGetSymbolAddress((void**)&ph1, g_h1);
    float* pk2 = nullptr; cudaGetSymbolAddress((void**)&pk2, g_k2);
    float* pdv = nullptr; cudaGetSymbolAddress((void**)&pdv, g_dv);

    const float scale = 1.0f / 32.0f;  // 1024^-0.5

    // 1) x = LN(inputs); e0 = LN(mu + exp(ls)*noise)
    ln_kernel<<<N_NODES, 256>>>(inputs, g_in, b_in, px, DIM);
    edge_ln_kernel<<<N_EDGE, 256>>>(noise, emu, elogsig, g_e, b_e, pe0);

    // 2) big node-side GEMMs
    {
        dim3 grid(DIM / 64, N_NODES / 64);
        gemm_nn<1><<<grid, 256>>>(px, Wk, bk, pk,  N_NODES, DIM, DIM);
        gemm_nn<1><<<grid, 256>>>(px, Wv, bv, pv,  N_NODES, DIM, DIM);
        gemm_nn<0><<<grid, 256>>>(px, Wq, bq, pq2, N_NODES, DIM, DIM);
    }
    // 3) q = relu(e0 @ Wq + bq)
    {
        dim3 grid(DIM / 64, N_EDGE / 64);
        gemm_nn<1><<<grid, 256>>>(pe0, Wq, bq, pq, N_EDGE, DIM, DIM);
    }
    // 4) dots = q @ k^T * scale  -> straight into output
    {
        dim3 grid(N_NODES / 64, N_EDGE / 64);
        gemm_nt<<<grid, 256>>>(pq, pk, out_dots, N_EDGE, N_NODES, DIM, scale);
    }
    // 5) cat = [e0 | updates]; updates via sparse top-k attention
    cat_copy_kernel<<<N_EDGE, 256>>>(pe0, pcat);
    attn_update_kernel<<<N_EDGE, 256>>>(out_dots, pv, kn, pcat);

    // 6) MLP: h1 = relu(cat @ W1 + b1); edges_out = h1 @ W2 + b2
    {
        dim3 grid(HID / 64, N_EDGE / 64);
        gemm_nn<1><<<grid, 256>>>(pcat, W1, b1, ph1, N_EDGE, HID, 2 * DIM);
    }
    {
        dim3 grid(DIM / 64, N_EDGE / 64);
        gemm_nn<0><<<grid, 256>>>(ph1, W2, b2, out_edges, N_EDGE, DIM, DIM);
    }
    // 7) k2 = relu(edges_out @ Wk + bk)
    {
        dim3 grid(DIM / 64, N_EDGE / 64);
        gemm_nn<1><<<grid, 256>>>(out_edges, Wk, bk, pk2, N_EDGE, DIM, DIM);
    }
    // 8) dots_v = q2 @ k2^T * scale; H = mask_topk(softmax(dots_v), k_e)
    {
        dim3 grid(N_EDGE / 64, N_NODES / 64);
        gemm_nt<<<grid, 256>>>(pq2, pk2, pdv, N_NODES, N_EDGE, DIM, scale);
    }
    h_kernel<<<N_NODES, 128>>>(pdv, ke, out_H);
}